// round 9
// baseline (speedup 1.0000x reference)
#include <cuda_runtime.h>
#include <cuda_fp16.h>
#include <cstdint>

#define B_     8
#define Q_     500
#define C_     256
#define S_     8
#define QPB    4
#define ROWS   32           // QPB * S_
#define NPIX_  8500
#define SSCALE 0.077f

// dynamic smem layout (bytes)
#define SM_A     0          // 32 x 256 fp16 = 16384
#define SM_IDX   16384      // 32*4 int   = 512
#define SM_WB    16896      // 32*4 float = 512
#define SM_SPT   17408      // 32*2 float = 256
#define SM_B1    17664      // 256 float  = 1024
#define SM_W2    18688      // 256 float4 = 4096
#define SM_PART  22784      // 4 x 32 float4 = 2048
#define SM_TOTAL 24832

__constant__ int c_lvl_h[4]  = {80, 40, 20, 10};
__constant__ int c_lvl_st[4] = {0, 6400, 8000, 8400};

// W1 pre-packed into mma.sync fp16 B-fragment order:
// uint2 per (k16 chunk kk, n8 tile nn, lane): {b0, b1}
__device__ __align__(8) uint2 g_w1b[16 * 32 * 32];

__device__ __forceinline__ float fast_tanh(float x) {
    float y; asm("tanh.approx.f32 %0, %1;" : "=f"(y) : "f"(x)); return y;
}
__device__ __forceinline__ uint32_t smem_u32(const void* p) {
    uint32_t a;
    asm("{ .reg .u64 t; cvta.to.shared.u64 t, %1; cvt.u32.u64 %0, t; }" : "=r"(a) : "l"(p));
    return a;
}
__device__ __forceinline__ void ldmatrix_x4(uint32_t& r0, uint32_t& r1,
                                            uint32_t& r2, uint32_t& r3, uint32_t addr) {
    asm volatile("ldmatrix.sync.aligned.m8n8.x4.shared.b16 {%0,%1,%2,%3}, [%4];"
                 : "=r"(r0), "=r"(r1), "=r"(r2), "=r"(r3) : "r"(addr));
}
__device__ __forceinline__ void mma_f16(float* d, const uint32_t* a,
                                        uint32_t b0, uint32_t b1) {
    asm volatile("mma.sync.aligned.m16n8k16.row.col.f32.f16.f16.f32 "
                 "{%0,%1,%2,%3}, {%4,%5,%6,%7}, {%8,%9}, {%0,%1,%2,%3};"
                 : "+f"(d[0]), "+f"(d[1]), "+f"(d[2]), "+f"(d[3])
                 : "r"(a[0]), "r"(a[1]), "r"(a[2]), "r"(a[3]), "r"(b0), "r"(b1));
}

// ---- prep: W1 fp32 [K=256][N=256] -> fp16 B-fragment order -------------------
__global__ void prep_w1(const float* __restrict__ W1) {
    const int k = blockIdx.x;    // K row
    const int n = threadIdx.x;   // N col
    float v = __ldg(W1 + k * 256 + n);
    __half hv = __float2half_rn(v);

    const int kk = k >> 4, kr = k & 15;
    const int nn = n >> 3, ncell = n & 7;
    const int lane = ncell * 4 + ((kr & 7) >> 1);
    const int r = kr >> 3;       // which reg (k rows 0-7 vs 8-15)
    const int h = kr & 1;        // halfword within reg
    uint16_t* dst = (uint16_t*)g_w1b;
    const int entry = ((kk * 32 + nn) * 32 + lane);
    dst[entry * 4 + r * 2 + h] = *(uint16_t*)&hv;
}

// ---- main --------------------------------------------------------------------
__global__ __launch_bounds__(128, 6)
void decoder_kernel(const float* __restrict__ ref_polys,
                    const int*   __restrict__ ref_levels,
                    const float* __restrict__ memory,
                    const float* __restrict__ b1,
                    const float* __restrict__ W2,
                    const float* __restrict__ b2,
                    float* __restrict__ out)
{
    extern __shared__ __align__(16) char smem[];
    const uint32_t sb = smem_u32(smem);
    const int tid  = threadIdx.x;
    const int wid  = tid >> 5;
    const int lane = tid & 31;
    const int bq0  = blockIdx.x * QPB;

    int*    s_idx  = (int*)   (smem + SM_IDX);
    float*  s_w    = (float*) (smem + SM_WB);
    float*  s_spt  = (float*) (smem + SM_SPT);
    float*  b1s    = (float*) (smem + SM_B1);
    float4* w2s    = (float4*)(smem + SM_W2);
    float4* s_part = (float4*)(smem + SM_PART);

    // ---- stage 1: sampling points + bilinear corners (threads 0..31) ----
    if (tid < ROWS) {
        const int qi = tid >> 3, s = tid & 7;
        const int bq = bq0 + qi;
        const int b  = bq / Q_;
        const float lam = (float)s * (1.0f / 7.0f);
        const float* rp = ref_polys + (size_t)bq * 8;
        float px = ((rp[0]*lam + rp[1])*lam + rp[2])*lam + rp[3];
        float py = ((rp[4]*lam + rp[5])*lam + rp[6])*lam + rp[7];
        float sx = 2.0f*(px - 0.5f), sy = 2.0f*(py - 0.5f);
        s_spt[tid*2 + 0] = sx;
        s_spt[tid*2 + 1] = sy;

        const int lvl = ref_levels[bq];
        const int H = c_lvl_h[lvl], W = H;
        const int base = b * NPIX_ + c_lvl_st[lvl];
        float gx = (sx + 1.0f) * 0.5f * (float)W - 0.5f;
        float gy = (sy + 1.0f) * 0.5f * (float)H - 0.5f;
        float x0 = floorf(gx), y0 = floorf(gy);
        float wx1 = gx - x0, wx0 = 1.0f - wx1;
        float wy1 = gy - y0, wy0 = 1.0f - wy1;
        #pragma unroll
        for (int k = 0; k < 4; k++) {
            float xf = (k & 1) ? (x0 + 1.0f) : x0;
            float yf = (k & 2) ? (y0 + 1.0f) : y0;
            float wx = (k & 1) ? wx1 : wx0;
            float wy = (k & 2) ? wy1 : wy0;
            bool valid = (xf >= 0.0f) && (xf <= (float)(W-1)) &&
                         (yf >= 0.0f) && (yf <= (float)(H-1));
            int xc = (int)fminf(fmaxf(xf, 0.0f), (float)(W-1));
            int yc = (int)fminf(fmaxf(yf, 0.0f), (float)(H-1));
            s_idx[tid*4 + k] = (base + yc * W + xc) * C_;
            s_w[tid*4 + k]   = valid ? (wy * wx) : 0.0f;
        }
    }
    b1s[tid]       = __ldg(b1 + tid);
    b1s[tid + 128] = __ldg(b1 + tid + 128);
    w2s[tid]       = __ldg((const float4*)W2 + tid);
    w2s[tid + 128] = __ldg((const float4*)W2 + tid + 128);
    __syncthreads();

    // ---- stage 2: gather -> A fp16 tile, XOR-swizzled rows of 512B ----
    {
        const int p2 = tid;             // channel pair 0..127
        #pragma unroll 4
        for (int m = 0; m < ROWS; m++) {
            int4   id = *(const int4*  )(s_idx + m * 4);
            float4 w  = *(const float4*)(s_w   + m * 4);
            float2 v0 = __ldg((const float2*)(memory + id.x) + p2);
            float2 v1 = __ldg((const float2*)(memory + id.y) + p2);
            float2 v2 = __ldg((const float2*)(memory + id.z) + p2);
            float2 v3 = __ldg((const float2*)(memory + id.w) + p2);
            float e0 = w.x*v0.x; e0 = fmaf(w.y, v1.x, e0);
            e0 = fmaf(w.z, v2.x, e0); e0 = fmaf(w.w, v3.x, e0);
            float e1 = w.x*v0.y; e1 = fmaf(w.y, v1.y, e1);
            e1 = fmaf(w.z, v2.y, e1); e1 = fmaf(w.w, v3.y, e1);

            uint32_t h2;
            asm("cvt.rn.f16x2.f32 %0, %1, %2;" : "=r"(h2) : "f"(e1), "f"(e0));

            uint32_t byte = (uint32_t)m * 512u + (uint32_t)p2 * 4u;
            byte ^= (uint32_t)(m & 7) << 4;
            *(uint32_t*)(smem + SM_A + byte) = h2;
        }
    }
    __syncthreads();

    // ---- stage 3: fp16 HMMA GEMM1 + fused GEMM2 projection ----
    // warp wid handles cols [wid*64, +64) over all 32 rows, in two 32-col chunks
    float p[4][4];
    #pragma unroll
    for (int i = 0; i < 4; i++)
        #pragma unroll
        for (int j = 0; j < 4; j++) p[i][j] = 0.0f;

    #pragma unroll
    for (int nc = 0; nc < 2; nc++) {
        const int nb = wid * 64 + nc * 32;   // global col base for this chunk
        float acc[2][4][4];
        #pragma unroll
        for (int mt = 0; mt < 2; mt++)
            #pragma unroll
            for (int nt = 0; nt < 4; nt++)
                #pragma unroll
                for (int d = 0; d < 4; d++) acc[mt][nt][d] = 0.0f;

        #pragma unroll 2
        for (int kk = 0; kk < 16; kk++) {
            uint2 bfr[4];
            #pragma unroll
            for (int nt = 0; nt < 4; nt++) {
                const int nn = (nb >> 3) + nt;
                bfr[nt] = __ldg(&g_w1b[(kk * 32 + nn) * 32 + lane]);
            }
            #pragma unroll
            for (int mt = 0; mt < 2; mt++) {
                const int jm = lane >> 3;
                const int mrow = mt * 16 + (lane & 7) + (jm & 1) * 8;
                const int kcol = kk * 16 + (jm >> 1) * 8;
                uint32_t byte = (uint32_t)mrow * 512u + (uint32_t)kcol * 2u;
                byte ^= (uint32_t)(mrow & 7) << 4;
                uint32_t af[4];
                ldmatrix_x4(af[0], af[1], af[2], af[3], sb + SM_A + byte);
                #pragma unroll
                for (int nt = 0; nt < 4; nt++)
                    mma_f16(acc[mt][nt], af, bfr[nt].x, bfr[nt].y);
            }
        }

        // chunk epilogue: tanh(d + b1) projected through W2 into p
        #pragma unroll
        for (int mt = 0; mt < 2; mt++)
            #pragma unroll
            for (int nt = 0; nt < 4; nt++)
                #pragma unroll
                for (int d = 0; d < 4; d++) {
                    const int col = nb + nt * 8 + (lane & 3) * 2 + (d & 1);
                    float h = fast_tanh(acc[mt][nt][d] + b1s[col]);
                    float4 w2 = w2s[col];
                    const int slot = mt * 2 + (d >> 1);
                    p[slot][0] = fmaf(h, w2.x, p[slot][0]);
                    p[slot][1] = fmaf(h, w2.y, p[slot][1]);
                    p[slot][2] = fmaf(h, w2.z, p[slot][2]);
                    p[slot][3] = fmaf(h, w2.w, p[slot][3]);
                }
    }

    // reduce the 4 lanes sharing the same rows (lane^1, lane^2)
    #pragma unroll
    for (int m = 1; m <= 2; m <<= 1)
        #pragma unroll
        for (int i = 0; i < 4; i++)
            #pragma unroll
            for (int j = 0; j < 4; j++)
                p[i][j] += __shfl_xor_sync(0xffffffffu, p[i][j], m);

    if ((lane & 3) == 0) {
        #pragma unroll
        for (int slot = 0; slot < 4; slot++) {
            const int mt = slot >> 1, rh = slot & 1;
            const int row = mt * 16 + (lane >> 2) + 8 * rh;
            s_part[wid * 32 + row] =
                make_float4(p[slot][0], p[slot][1], p[slot][2], p[slot][3]);
        }
    }
    __syncthreads();

    // ---- stage 4: final combine + output (threads 0..31, one M-row each) ----
    if (tid < ROWS) {
        float4 a0 = s_part[0 * 32 + tid];
        float4 a1 = s_part[1 * 32 + tid];
        float4 a2 = s_part[2 * 32 + tid];
        float4 a3 = s_part[3 * 32 + tid];
        float v0 = a0.x + a1.x + a2.x + a3.x;
        float v1 = a0.y + a1.y + a2.y + a3.y;
        float v2 = a0.z + a1.z + a2.z + a3.z;
        float v3 = a0.w + a1.w + a2.w + a3.w;
        const int qi = tid >> 3, s = tid & 7;
        const float sx = s_spt[tid*2 + 0], sy = s_spt[tid*2 + 1];
        float4 bb = __ldg((const float4*)b2);
        float4 o;
        o.x = SSCALE * fast_tanh(v0 + bb.x) + sx;
        o.y = SSCALE * fast_tanh(v1 + bb.y) + sy;
        o.z = SSCALE * fast_tanh(v2 + bb.z) + sx;
        o.w = SSCALE * fast_tanh(v3 + bb.w) + sy;
        *(float4*)(out + (size_t)(bq0 + qi) * 32 + s * 4) = o;
    }
}

extern "C" void kernel_launch(void* const* d_in, const int* in_sizes, int n_in,
                              void* d_out, int out_size)
{
    const float* ref_polys  = (const float*)d_in[0];
    const int*   ref_levels = (const int*  )d_in[1];
    const float* memory     = (const float*)d_in[2];
    const float* W1         = (const float*)d_in[3];
    const float* b1         = (const float*)d_in[4];
    const float* W2         = (const float*)d_in[5];
    const float* b2         = (const float*)d_in[6];
    float* out = (float*)d_out;

    prep_w1<<<256, 256>>>(W1);
    decoder_kernel<<<(B_ * Q_) / QPB, 128, SM_TOTAL>>>(
        ref_polys, ref_levels, memory, b1, W2, b2, out);
}

// round 10
// speedup vs baseline: 1.1290x; 1.1290x over previous
#include <cuda_runtime.h>
#include <cuda_fp16.h>
#include <cstdint>

#define B_     8
#define Q_     500
#define C_     256
#define S_     8
#define QPB    4
#define ROWS   32           // QPB * S_
#define NPIX_  8500
#define SSCALE 0.077f

// dynamic smem layout (bytes)
#define SM_A     0          // 32 x 256 fp16 = 16384
#define SM_IDX   16384      // 32*4 int   = 512
#define SM_WB    16896      // 32*4 float = 512
#define SM_SPT   17408      // 32*2 float = 256
#define SM_B1    17664      // 256 float  = 1024
#define SM_W2    18688      // 256 float4 = 4096
#define SM_PART  22784      // 4 x 32 float4 = 2048
#define SM_TOTAL 24832

__constant__ int c_lvl_h[4]  = {80, 40, 20, 10};
__constant__ int c_lvl_st[4] = {0, 6400, 8000, 8400};

// W1 pre-packed into mma.sync fp16 B-fragment order:
// uint2 per (k16 chunk kk, n8 tile nn, lane): {b0, b1}
__device__ __align__(8) uint2 g_w1b[16 * 32 * 32];

__device__ __forceinline__ float fast_tanh(float x) {
    float y; asm("tanh.approx.f32 %0, %1;" : "=f"(y) : "f"(x)); return y;
}
__device__ __forceinline__ uint32_t smem_u32(const void* p) {
    uint32_t a;
    asm("{ .reg .u64 t; cvta.to.shared.u64 t, %1; cvt.u32.u64 %0, t; }" : "=r"(a) : "l"(p));
    return a;
}
__device__ __forceinline__ void ldmatrix_x4(uint32_t& r0, uint32_t& r1,
                                            uint32_t& r2, uint32_t& r3, uint32_t addr) {
    asm volatile("ldmatrix.sync.aligned.m8n8.x4.shared.b16 {%0,%1,%2,%3}, [%4];"
                 : "=r"(r0), "=r"(r1), "=r"(r2), "=r"(r3) : "r"(addr));
}
__device__ __forceinline__ void mma_f16(float* d, const uint32_t* a,
                                        uint32_t b0, uint32_t b1) {
    asm volatile("mma.sync.aligned.m16n8k16.row.col.f32.f16.f16.f32 "
                 "{%0,%1,%2,%3}, {%4,%5,%6,%7}, {%8,%9}, {%0,%1,%2,%3};"
                 : "+f"(d[0]), "+f"(d[1]), "+f"(d[2]), "+f"(d[3])
                 : "r"(a[0]), "r"(a[1]), "r"(a[2]), "r"(a[3]), "r"(b0), "r"(b1));
}

// ---- prep: W1 fp32 [K=256][N=256] -> fp16 B-fragment order -------------------
__global__ void prep_w1(const float* __restrict__ W1) {
    const int k = blockIdx.x;    // K row
    const int n = threadIdx.x;   // N col
    float v = __ldg(W1 + k * 256 + n);
    __half hv = __float2half_rn(v);

    const int kk = k >> 4, kr = k & 15;
    const int nn = n >> 3, ncell = n & 7;
    const int lane = ncell * 4 + ((kr & 7) >> 1);
    const int r = kr >> 3;       // which reg (k rows 0-7 vs 8-15)
    const int h = kr & 1;        // halfword within reg
    uint16_t* dst = (uint16_t*)g_w1b;
    const int entry = ((kk * 32 + nn) * 32 + lane);
    dst[entry * 4 + r * 2 + h] = *(uint16_t*)&hv;
}

// ---- main --------------------------------------------------------------------
__global__ __launch_bounds__(128, 8)
void decoder_kernel(const float* __restrict__ ref_polys,
                    const int*   __restrict__ ref_levels,
                    const float* __restrict__ memory,
                    const float* __restrict__ b1,
                    const float* __restrict__ W2,
                    const float* __restrict__ b2,
                    float* __restrict__ out)
{
    extern __shared__ __align__(16) char smem[];
    const uint32_t sb = smem_u32(smem);
    const int tid  = threadIdx.x;
    const int wid  = tid >> 5;
    const int lane = tid & 31;
    const int bq0  = blockIdx.x * QPB;

    int*    s_idx  = (int*)   (smem + SM_IDX);
    float*  s_w    = (float*) (smem + SM_WB);
    float*  s_spt  = (float*) (smem + SM_SPT);
    float*  b1s    = (float*) (smem + SM_B1);
    float4* w2s    = (float4*)(smem + SM_W2);
    float4* s_part = (float4*)(smem + SM_PART);

    // ---- stage 1: sampling points + bilinear corners (threads 0..31) ----
    if (tid < ROWS) {
        const int qi = tid >> 3, s = tid & 7;
        const int bq = bq0 + qi;
        const int b  = bq / Q_;
        const float lam = (float)s * (1.0f / 7.0f);
        const float* rp = ref_polys + (size_t)bq * 8;
        float px = ((rp[0]*lam + rp[1])*lam + rp[2])*lam + rp[3];
        float py = ((rp[4]*lam + rp[5])*lam + rp[6])*lam + rp[7];
        float sx = 2.0f*(px - 0.5f), sy = 2.0f*(py - 0.5f);
        s_spt[tid*2 + 0] = sx;
        s_spt[tid*2 + 1] = sy;

        const int lvl = ref_levels[bq];
        const int H = c_lvl_h[lvl], W = H;
        const int base = b * NPIX_ + c_lvl_st[lvl];
        float gx = (sx + 1.0f) * 0.5f * (float)W - 0.5f;
        float gy = (sy + 1.0f) * 0.5f * (float)H - 0.5f;
        float x0 = floorf(gx), y0 = floorf(gy);
        float wx1 = gx - x0, wx0 = 1.0f - wx1;
        float wy1 = gy - y0, wy0 = 1.0f - wy1;
        #pragma unroll
        for (int k = 0; k < 4; k++) {
            float xf = (k & 1) ? (x0 + 1.0f) : x0;
            float yf = (k & 2) ? (y0 + 1.0f) : y0;
            float wx = (k & 1) ? wx1 : wx0;
            float wy = (k & 2) ? wy1 : wy0;
            bool valid = (xf >= 0.0f) && (xf <= (float)(W-1)) &&
                         (yf >= 0.0f) && (yf <= (float)(H-1));
            int xc = (int)fminf(fmaxf(xf, 0.0f), (float)(W-1));
            int yc = (int)fminf(fmaxf(yf, 0.0f), (float)(H-1));
            s_idx[tid*4 + k] = (base + yc * W + xc) * C_;
            s_w[tid*4 + k]   = valid ? (wy * wx) : 0.0f;
        }
    }
    b1s[tid]       = __ldg(b1 + tid);
    b1s[tid + 128] = __ldg(b1 + tid + 128);
    w2s[tid]       = __ldg((const float4*)W2 + tid);
    w2s[tid + 128] = __ldg((const float4*)W2 + tid + 128);
    __syncthreads();

    // ---- stage 2: gather -> A fp16 tile, XOR-swizzled rows of 512B ----
    {
        const int p2 = tid;             // channel pair 0..127
        #pragma unroll 4
        for (int m = 0; m < ROWS; m++) {
            int4   id = *(const int4*  )(s_idx + m * 4);
            float4 w  = *(const float4*)(s_w   + m * 4);
            float2 v0 = __ldg((const float2*)(memory + id.x) + p2);
            float2 v1 = __ldg((const float2*)(memory + id.y) + p2);
            float2 v2 = __ldg((const float2*)(memory + id.z) + p2);
            float2 v3 = __ldg((const float2*)(memory + id.w) + p2);
            float e0 = w.x*v0.x; e0 = fmaf(w.y, v1.x, e0);
            e0 = fmaf(w.z, v2.x, e0); e0 = fmaf(w.w, v3.x, e0);
            float e1 = w.x*v0.y; e1 = fmaf(w.y, v1.y, e1);
            e1 = fmaf(w.z, v2.y, e1); e1 = fmaf(w.w, v3.y, e1);

            uint32_t h2;
            asm("cvt.rn.f16x2.f32 %0, %1, %2;" : "=r"(h2) : "f"(e1), "f"(e0));

            uint32_t byte = (uint32_t)m * 512u + (uint32_t)p2 * 4u;
            byte ^= (uint32_t)(m & 7) << 4;
            *(uint32_t*)(smem + SM_A + byte) = h2;
        }
    }
    __syncthreads();

    // ---- stage 3: fp16 HMMA GEMM1 + fused GEMM2 projection ----
    // warp wid: cols [wid*64, +64) over 32 rows; nc chunks of 32 cols; mt outer
    // to keep only acc[4][4] live in the K loop (reg budget 64 for 8 blocks/SM).
    #pragma unroll
    for (int nc = 0; nc < 2; nc++) {
        const int nb = wid * 64 + nc * 32;
        #pragma unroll
        for (int mt = 0; mt < 2; mt++) {
            float acc[4][4];
            #pragma unroll
            for (int nt = 0; nt < 4; nt++)
                #pragma unroll
                for (int d = 0; d < 4; d++) acc[nt][d] = 0.0f;

            #pragma unroll 2
            for (int kk = 0; kk < 16; kk++) {
                const int jm = lane >> 3;
                const int mrow = mt * 16 + (lane & 7) + (jm & 1) * 8;
                const int kcol = kk * 16 + (jm >> 1) * 8;
                uint32_t byte = (uint32_t)mrow * 512u + (uint32_t)kcol * 2u;
                byte ^= (uint32_t)(mrow & 7) << 4;
                uint32_t af[4];
                ldmatrix_x4(af[0], af[1], af[2], af[3], sb + SM_A + byte);
                #pragma unroll
                for (int nt = 0; nt < 4; nt++) {
                    const int nn = (nb >> 3) + nt;
                    uint2 bfr = __ldg(&g_w1b[(kk * 32 + nn) * 32 + lane]);
                    mma_f16(acc[nt], af, bfr.x, bfr.y);
                }
            }

            // epilogue for this (nc, mt): tanh + W2 projection, 2 row-slots
            float p[2][4];
            #pragma unroll
            for (int rh = 0; rh < 2; rh++)
                #pragma unroll
                for (int j = 0; j < 4; j++) p[rh][j] = 0.0f;

            #pragma unroll
            for (int nt = 0; nt < 4; nt++)
                #pragma unroll
                for (int d = 0; d < 4; d++) {
                    const int col = nb + nt * 8 + (lane & 3) * 2 + (d & 1);
                    float h = fast_tanh(acc[nt][d] + b1s[col]);
                    float4 w2 = w2s[col];
                    const int rh = d >> 1;
                    p[rh][0] = fmaf(h, w2.x, p[rh][0]);
                    p[rh][1] = fmaf(h, w2.y, p[rh][1]);
                    p[rh][2] = fmaf(h, w2.z, p[rh][2]);
                    p[rh][3] = fmaf(h, w2.w, p[rh][3]);
                }

            // reduce across the 4 lanes sharing a row (lane^1, lane^2)
            #pragma unroll
            for (int m = 1; m <= 2; m <<= 1)
                #pragma unroll
                for (int rh = 0; rh < 2; rh++)
                    #pragma unroll
                    for (int j = 0; j < 4; j++)
                        p[rh][j] += __shfl_xor_sync(0xffffffffu, p[rh][j], m);

            if ((lane & 3) == 0) {
                #pragma unroll
                for (int rh = 0; rh < 2; rh++) {
                    const int row = mt * 16 + (lane >> 2) + 8 * rh;
                    float4 v = make_float4(p[rh][0], p[rh][1], p[rh][2], p[rh][3]);
                    if (nc == 0) {
                        s_part[wid * 32 + row] = v;
                    } else {
                        float4 o = s_part[wid * 32 + row];
                        o.x += v.x; o.y += v.y; o.z += v.z; o.w += v.w;
                        s_part[wid * 32 + row] = o;
                    }
                }
            }
        }
    }
    __syncthreads();

    // ---- stage 4: final combine + output (threads 0..31, one M-row each) ----
    if (tid < ROWS) {
        float4 a0 = s_part[0 * 32 + tid];
        float4 a1 = s_part[1 * 32 + tid];
        float4 a2 = s_part[2 * 32 + tid];
        float4 a3 = s_part[3 * 32 + tid];
        float v0 = a0.x + a1.x + a2.x + a3.x;
        float v1 = a0.y + a1.y + a2.y + a3.y;
        float v2 = a0.z + a1.z + a2.z + a3.z;
        float v3 = a0.w + a1.w + a2.w + a3.w;
        const int qi = tid >> 3, s = tid & 7;
        const float sx = s_spt[tid*2 + 0], sy = s_spt[tid*2 + 1];
        float4 bb = __ldg((const float4*)b2);
        float4 o;
        o.x = SSCALE * fast_tanh(v0 + bb.x) + sx;
        o.y = SSCALE * fast_tanh(v1 + bb.y) + sy;
        o.z = SSCALE * fast_tanh(v2 + bb.z) + sx;
        o.w = SSCALE * fast_tanh(v3 + bb.w) + sy;
        *(float4*)(out + (size_t)(bq0 + qi) * 32 + s * 4) = o;
    }
}

extern "C" void kernel_launch(void* const* d_in, const int* in_sizes, int n_in,
                              void* d_out, int out_size)
{
    const float* ref_polys  = (const float*)d_in[0];
    const int*   ref_levels = (const int*  )d_in[1];
    const float* memory     = (const float*)d_in[2];
    const float* W1         = (const float*)d_in[3];
    const float* b1         = (const float*)d_in[4];
    const float* W2         = (const float*)d_in[5];
    const float* b2         = (const float*)d_in[6];
    float* out = (float*)d_out;

    prep_w1<<<256, 256>>>(W1);
    decoder_kernel<<<(B_ * Q_) / QPB, 128, SM_TOTAL>>>(
        ref_polys, ref_levels, memory, b1, W2, b2, out);
}

// round 12
// speedup vs baseline: 1.3368x; 1.1840x over previous
#include <cuda_runtime.h>
#include <cuda_fp16.h>
#include <cstdint>

#define B_     8
#define Q_     500
#define C_     256
#define S_     8
#define QPB    4
#define ROWS   32           // QPB * S_
#define NPIX_  8500
#define SSCALE 0.077f

// dynamic smem layout (bytes)
#define SM_A     0          // 32 x 256 fp16 = 16384
#define SM_IDX   16384      // 32*4 int   = 512
#define SM_WB    16896      // 32*4 float = 512
#define SM_SPT   17408      // 32*2 float = 256
#define SM_B1    17664      // 256 float  = 1024
#define SM_W2    18688      // 256 float4 = 4096
#define SM_PART  22784      // 4 x 32 float4 = 2048
#define SM_TOTAL 24832

__constant__ int c_lvl_h[4]  = {80, 40, 20, 10};
__constant__ int c_lvl_st[4] = {0, 6400, 8000, 8400};

// W1 pre-packed into mma.sync fp16 B-fragment order:
// uint2 per (k16 chunk kk, n8 tile nn, lane): {b0, b1}
__device__ __align__(8) uint2 g_w1b[16 * 32 * 32];

__device__ __forceinline__ float fast_tanh(float x) {
    float y; asm("tanh.approx.f32 %0, %1;" : "=f"(y) : "f"(x)); return y;
}
__device__ __forceinline__ uint32_t smem_u32(const void* p) {
    uint32_t a;
    asm("{ .reg .u64 t; cvta.to.shared.u64 t, %1; cvt.u32.u64 %0, t; }" : "=r"(a) : "l"(p));
    return a;
}
__device__ __forceinline__ void ldmatrix_x4(uint32_t& r0, uint32_t& r1,
                                            uint32_t& r2, uint32_t& r3, uint32_t addr) {
    asm volatile("ldmatrix.sync.aligned.m8n8.x4.shared.b16 {%0,%1,%2,%3}, [%4];"
                 : "=r"(r0), "=r"(r1), "=r"(r2), "=r"(r3) : "r"(addr));
}
__device__ __forceinline__ void mma_f16(float* d, const uint32_t* a,
                                        uint32_t b0, uint32_t b1) {
    asm volatile("mma.sync.aligned.m16n8k16.row.col.f32.f16.f16.f32 "
                 "{%0,%1,%2,%3}, {%4,%5,%6,%7}, {%8,%9}, {%0,%1,%2,%3};"
                 : "+f"(d[0]), "+f"(d[1]), "+f"(d[2]), "+f"(d[3])
                 : "r"(a[0]), "r"(a[1]), "r"(a[2]), "r"(a[3]), "r"(b0), "r"(b1));
}

// ---- prep: W1 fp32 [K=256][N=256] -> fp16 B-fragment order -------------------
__global__ void prep_w1(const float* __restrict__ W1) {
    const int k = blockIdx.x;    // K row
    const int n = threadIdx.x;   // N col
    float v = __ldg(W1 + k * 256 + n);
    __half hv = __float2half_rn(v);

    const int kk = k >> 4, kr = k & 15;
    const int nn = n >> 3, ncell = n & 7;
    const int lane = ncell * 4 + ((kr & 7) >> 1);
    const int r = kr >> 3;       // which reg (k rows 0-7 vs 8-15)
    const int h = kr & 1;        // halfword within reg
    uint16_t* dst = (uint16_t*)g_w1b;
    const int entry = ((kk * 32 + nn) * 32 + lane);
    dst[entry * 4 + r * 2 + h] = *(uint16_t*)&hv;
}

// ---- main --------------------------------------------------------------------
__global__ __launch_bounds__(128, 7)
void decoder_kernel(const float* __restrict__ ref_polys,
                    const int*   __restrict__ ref_levels,
                    const float* __restrict__ memory,
                    const float* __restrict__ b1,
                    const float* __restrict__ W2,
                    const float* __restrict__ b2,
                    float* __restrict__ out)
{
    extern __shared__ __align__(16) char smem[];
    const uint32_t sb = smem_u32(smem);
    const int tid  = threadIdx.x;
    const int wid  = tid >> 5;
    const int lane = tid & 31;
    const int bq0  = blockIdx.x * QPB;

    int*    s_idx  = (int*)   (smem + SM_IDX);
    float*  s_w    = (float*) (smem + SM_WB);
    float*  s_spt  = (float*) (smem + SM_SPT);
    float*  b1s    = (float*) (smem + SM_B1);
    float4* w2s    = (float4*)(smem + SM_W2);
    float4* s_part = (float4*)(smem + SM_PART);

    // ---- stage 1: sampling points + bilinear corners (threads 0..31) ----
    if (tid < ROWS) {
        const int qi = tid >> 3, s = tid & 7;
        const int bq = bq0 + qi;
        const int b  = bq / Q_;
        const float lam = (float)s * (1.0f / 7.0f);
        const float* rp = ref_polys + (size_t)bq * 8;
        float px = ((rp[0]*lam + rp[1])*lam + rp[2])*lam + rp[3];
        float py = ((rp[4]*lam + rp[5])*lam + rp[6])*lam + rp[7];
        float sx = 2.0f*(px - 0.5f), sy = 2.0f*(py - 0.5f);
        s_spt[tid*2 + 0] = sx;
        s_spt[tid*2 + 1] = sy;

        const int lvl = ref_levels[bq];
        const int H = c_lvl_h[lvl], W = H;
        const int base = b * NPIX_ + c_lvl_st[lvl];
        float gx = (sx + 1.0f) * 0.5f * (float)W - 0.5f;
        float gy = (sy + 1.0f) * 0.5f * (float)H - 0.5f;
        float x0 = floorf(gx), y0 = floorf(gy);
        float wx1 = gx - x0, wx0 = 1.0f - wx1;
        float wy1 = gy - y0, wy0 = 1.0f - wy1;
        #pragma unroll
        for (int k = 0; k < 4; k++) {
            float xf = (k & 1) ? (x0 + 1.0f) : x0;
            float yf = (k & 2) ? (y0 + 1.0f) : y0;
            float wx = (k & 1) ? wx1 : wx0;
            float wy = (k & 2) ? wy1 : wy0;
            bool valid = (xf >= 0.0f) && (xf <= (float)(W-1)) &&
                         (yf >= 0.0f) && (yf <= (float)(H-1));
            int xc = (int)fminf(fmaxf(xf, 0.0f), (float)(W-1));
            int yc = (int)fminf(fmaxf(yf, 0.0f), (float)(H-1));
            s_idx[tid*4 + k] = (base + yc * W + xc) * C_;
            s_w[tid*4 + k]   = valid ? (wy * wx) : 0.0f;
        }
    }
    b1s[tid]       = __ldg(b1 + tid);
    b1s[tid + 128] = __ldg(b1 + tid + 128);
    w2s[tid]       = __ldg((const float4*)W2 + tid);
    w2s[tid + 128] = __ldg((const float4*)W2 + tid + 128);
    __syncthreads();

    // ---- stage 2: gather -> A fp16 tile, XOR-swizzled rows of 512B ----
    // 64 threads per row-half; each thread owns a channel quad (LDG.128).
    {
        const int p4   = tid & 63;      // channel quad 0..63
        const int half = tid >> 6;      // rows [half*16, +16)
        #pragma unroll 4
        for (int r = 0; r < 16; r++) {
            const int m = half * 16 + r;
            int4   id = *(const int4*  )(s_idx + m * 4);
            float4 w  = *(const float4*)(s_w   + m * 4);
            float4 v0 = __ldg((const float4*)(memory + id.x) + p4);
            float4 v1 = __ldg((const float4*)(memory + id.y) + p4);
            float4 v2 = __ldg((const float4*)(memory + id.z) + p4);
            float4 v3 = __ldg((const float4*)(memory + id.w) + p4);
            float e0 = w.x*v0.x; e0 = fmaf(w.y, v1.x, e0);
            e0 = fmaf(w.z, v2.x, e0); e0 = fmaf(w.w, v3.x, e0);
            float e1 = w.x*v0.y; e1 = fmaf(w.y, v1.y, e1);
            e1 = fmaf(w.z, v2.y, e1); e1 = fmaf(w.w, v3.y, e1);
            float e2 = w.x*v0.z; e2 = fmaf(w.y, v1.z, e2);
            e2 = fmaf(w.z, v2.z, e2); e2 = fmaf(w.w, v3.z, e2);
            float e3 = w.x*v0.w; e3 = fmaf(w.y, v1.w, e3);
            e3 = fmaf(w.z, v2.w, e3); e3 = fmaf(w.w, v3.w, e3);

            uint2 h4;
            asm("cvt.rn.f16x2.f32 %0, %1, %2;" : "=r"(h4.x) : "f"(e1), "f"(e0));
            asm("cvt.rn.f16x2.f32 %0, %1, %2;" : "=r"(h4.y) : "f"(e3), "f"(e2));

            uint32_t byte = (uint32_t)m * 512u + (uint32_t)p4 * 8u;
            byte ^= (uint32_t)(m & 7) << 4;
            *(uint2*)(smem + SM_A + byte) = h4;
        }
    }
    __syncthreads();

    // ---- stage 3: fp16 HMMA GEMM1 + fused GEMM2 projection ----
    // warp wid: cols [wid*64, +64) in two 32-col chunks; bfr cached across mt
    // (B read once per warp), acc[2][4][4] live in the K loop.
    #pragma unroll
    for (int nc = 0; nc < 2; nc++) {
        const int nb = wid * 64 + nc * 32;
        float acc[2][4][4];
        #pragma unroll
        for (int mt = 0; mt < 2; mt++)
            #pragma unroll
            for (int nt = 0; nt < 4; nt++)
                #pragma unroll
                for (int d = 0; d < 4; d++) acc[mt][nt][d] = 0.0f;

        #pragma unroll 2
        for (int kk = 0; kk < 16; kk++) {
            uint2 bfr[4];
            #pragma unroll
            for (int nt = 0; nt < 4; nt++) {
                const int nn = (nb >> 3) + nt;
                bfr[nt] = __ldg(&g_w1b[(kk * 32 + nn) * 32 + lane]);
            }
            #pragma unroll
            for (int mt = 0; mt < 2; mt++) {
                const int jm = lane >> 3;
                const int mrow = mt * 16 + (lane & 7) + (jm & 1) * 8;
                const int kcol = kk * 16 + (jm >> 1) * 8;
                uint32_t byte = (uint32_t)mrow * 512u + (uint32_t)kcol * 2u;
                byte ^= (uint32_t)(mrow & 7) << 4;
                uint32_t af[4];
                ldmatrix_x4(af[0], af[1], af[2], af[3], sb + SM_A + byte);
                #pragma unroll
                for (int nt = 0; nt < 4; nt++)
                    mma_f16(acc[mt][nt], af, bfr[nt].x, bfr[nt].y);
            }
        }

        // chunk epilogue: tanh(d + b1) projected through W2
        #pragma unroll
        for (int mt = 0; mt < 2; mt++) {
            float p[2][4];
            #pragma unroll
            for (int rh = 0; rh < 2; rh++)
                #pragma unroll
                for (int j = 0; j < 4; j++) p[rh][j] = 0.0f;

            #pragma unroll
            for (int nt = 0; nt < 4; nt++)
                #pragma unroll
                for (int d = 0; d < 4; d++) {
                    const int col = nb + nt * 8 + (lane & 3) * 2 + (d & 1);
                    float h = fast_tanh(acc[mt][nt][d] + b1s[col]);
                    float4 w2 = w2s[col];
                    const int rh = d >> 1;
                    p[rh][0] = fmaf(h, w2.x, p[rh][0]);
                    p[rh][1] = fmaf(h, w2.y, p[rh][1]);
                    p[rh][2] = fmaf(h, w2.z, p[rh][2]);
                    p[rh][3] = fmaf(h, w2.w, p[rh][3]);
                }

            // reduce across the 4 lanes sharing a row (lane^1, lane^2)
            #pragma unroll
            for (int m = 1; m <= 2; m <<= 1)
                #pragma unroll
                for (int rh = 0; rh < 2; rh++)
                    #pragma unroll
                    for (int j = 0; j < 4; j++)
                        p[rh][j] += __shfl_xor_sync(0xffffffffu, p[rh][j], m);

            if ((lane & 3) == 0) {
                #pragma unroll
                for (int rh = 0; rh < 2; rh++) {
                    const int row = mt * 16 + (lane >> 2) + 8 * rh;
                    float4 v = make_float4(p[rh][0], p[rh][1], p[rh][2], p[rh][3]);
                    if (nc == 0) {
                        s_part[wid * 32 + row] = v;
                    } else {
                        float4 o = s_part[wid * 32 + row];
                        o.x += v.x; o.y += v.y; o.z += v.z; o.w += v.w;
                        s_part[wid * 32 + row] = o;
                    }
                }
            }
        }
    }
    __syncthreads();

    // ---- stage 4: final combine + output (threads 0..31, one M-row each) ----
    if (tid < ROWS) {
        float4 a0 = s_part[0 * 32 + tid];
        float4 a1 = s_part[1 * 32 + tid];
        float4 a2 = s_part[2 * 32 + tid];
        float4 a3 = s_part[3 * 32 + tid];
        float v0 = a0.x + a1.x + a2.x + a3.x;
        float v1 = a0.y + a1.y + a2.y + a3.y;
        float v2 = a0.z + a1.z + a2.z + a3.z;
        float v3 = a0.w + a1.w + a2.w + a3.w;
        const int qi = tid >> 3, s = tid & 7;
        const float sx = s_spt[tid*2 + 0], sy = s_spt[tid*2 + 1];
        float4 bb = __ldg((const float4*)b2);
        float4 o;
        o.x = SSCALE * fast_tanh(v0 + bb.x) + sx;
        o.y = SSCALE * fast_tanh(v1 + bb.y) + sy;
        o.z = SSCALE * fast_tanh(v2 + bb.z) + sx;
        o.w = SSCALE * fast_tanh(v3 + bb.w) + sy;
        *(float4*)(out + (size_t)(bq0 + qi) * 32 + s * 4) = o;
    }
}

extern "C" void kernel_launch(void* const* d_in, const int* in_sizes, int n_in,
                              void* d_out, int out_size)
{
    const float* ref_polys  = (const float*)d_in[0];
    const int*   ref_levels = (const int*  )d_in[1];
    const float* memory     = (const float*)d_in[2];
    const float* W1         = (const float*)d_in[3];
    const float* b1         = (const float*)d_in[4];
    const float* W2         = (const float*)d_in[5];
    const float* b2         = (const float*)d_in[6];
    float* out = (float*)d_out;

    prep_w1<<<256, 256>>>(W1);
    decoder_kernel<<<(B_ * Q_) / QPB, 128, SM_TOTAL>>>(
        ref_polys, ref_levels, memory, b1, W2, b2, out);
}

// round 15
// speedup vs baseline: 1.3636x; 1.0201x over previous
#include <cuda_runtime.h>
#include <cuda_fp16.h>
#include <cstdint>

#define B_     8
#define Q_     500
#define C_     256
#define S_     8
#define QPB    4
#define ROWS   32           // QPB * S_
#define NPIX_  8500
#define SSCALE 0.077f

// dynamic smem layout (bytes)
#define SM_A     0          // 32 x 256 fp16 = 16384
#define SM_IDX   16384      // 32*4 int   = 512
#define SM_WB    16896      // 32*4 float = 512
#define SM_SPT   17408      // 32*2 float = 256
#define SM_B1    17664      // 256 float  = 1024
#define SM_W2    18688      // 256 float4 = 4096
#define SM_PART  22784      // 4 x 32 float4 = 2048
#define SM_TOTAL 24832

__constant__ int c_lvl_h[4]  = {80, 40, 20, 10};
__constant__ int c_lvl_st[4] = {0, 6400, 8000, 8400};

// W1 pre-packed into mma.sync fp16 B-fragment order:
// uint2 per (k16 chunk kk, n8 tile nn, lane): {b0, b1}
__device__ __align__(8) uint2 g_w1b[16 * 32 * 32];

__device__ __forceinline__ float fast_tanh(float x) {
    float y; asm("tanh.approx.f32 %0, %1;" : "=f"(y) : "f"(x)); return y;
}
__device__ __forceinline__ uint32_t smem_u32(const void* p) {
    uint32_t a;
    asm("{ .reg .u64 t; cvta.to.shared.u64 t, %1; cvt.u32.u64 %0, t; }" : "=r"(a) : "l"(p));
    return a;
}
__device__ __forceinline__ void ldmatrix_x4(uint32_t& r0, uint32_t& r1,
                                            uint32_t& r2, uint32_t& r3, uint32_t addr) {
    asm volatile("ldmatrix.sync.aligned.m8n8.x4.shared.b16 {%0,%1,%2,%3}, [%4];"
                 : "=r"(r0), "=r"(r1), "=r"(r2), "=r"(r3) : "r"(addr));
}
__device__ __forceinline__ void mma_f16(float* d, const uint32_t* a,
                                        uint32_t b0, uint32_t b1) {
    asm volatile("mma.sync.aligned.m16n8k16.row.col.f32.f16.f16.f32 "
                 "{%0,%1,%2,%3}, {%4,%5,%6,%7}, {%8,%9}, {%0,%1,%2,%3};"
                 : "+f"(d[0]), "+f"(d[1]), "+f"(d[2]), "+f"(d[3])
                 : "r"(a[0]), "r"(a[1]), "r"(a[2]), "r"(a[3]), "r"(b0), "r"(b1));
}

// ---- prep: W1 fp32 [K=256][N=256] -> fp16 B-fragment order (dest-major) ------
// ONE THREAD PER uint2 ENTRY: 16*32*32 = 16384 entries -> <<<64, 256>>>.
// entry e = (kk*32 + nn)*32 + lane:
//   n = nn*8 + (lane>>2), kb = kk*16 + (lane&3)*2
//   halfwords {kb+0, kb+1, kb+8, kb+9}
__global__ void prep_w1(const float* __restrict__ W1) {
    const int e = blockIdx.x * 256 + threadIdx.x;   // entry 0..16383
    const int lane = e & 31;
    const int nn   = (e >> 5) & 31;
    const int kk   = e >> 10;                        // 0..15
    const int n    = nn * 8 + (lane >> 2);
    const int kb   = kk * 16 + (lane & 3) * 2;
    __half v0 = __float2half_rn(__ldg(W1 + (kb + 0) * 256 + n));
    __half v1 = __float2half_rn(__ldg(W1 + (kb + 1) * 256 + n));
    __half v2 = __float2half_rn(__ldg(W1 + (kb + 8) * 256 + n));
    __half v3 = __float2half_rn(__ldg(W1 + (kb + 9) * 256 + n));
    uint2 o;
    o.x = (uint32_t)*(uint16_t*)&v0 | ((uint32_t)*(uint16_t*)&v1 << 16);
    o.y = (uint32_t)*(uint16_t*)&v2 | ((uint32_t)*(uint16_t*)&v3 << 16);
    g_w1b[e] = o;
}

// ---- main --------------------------------------------------------------------
__global__ __launch_bounds__(128, 7)
void decoder_kernel(const float* __restrict__ ref_polys,
                    const int*   __restrict__ ref_levels,
                    const float* __restrict__ memory,
                    const float* __restrict__ b1,
                    const float* __restrict__ W2,
                    const float* __restrict__ b2,
                    float* __restrict__ out)
{
    extern __shared__ __align__(16) char smem[];
    const uint32_t sb = smem_u32(smem);
    const int tid  = threadIdx.x;
    const int wid  = tid >> 5;
    const int lane = tid & 31;
    const int bq0  = blockIdx.x * QPB;

    int*    s_idx  = (int*)   (smem + SM_IDX);
    float*  s_w    = (float*) (smem + SM_WB);
    float*  s_spt  = (float*) (smem + SM_SPT);
    float*  b1s    = (float*) (smem + SM_B1);
    float4* w2s    = (float4*)(smem + SM_W2);
    float4* s_part = (float4*)(smem + SM_PART);

    // ---- stage 1: sampling points + bilinear corners (threads 0..31) ----
    if (tid < ROWS) {
        const int qi = tid >> 3, s = tid & 7;
        const int bq = bq0 + qi;
        const int b  = bq / Q_;
        const float lam = (float)s * (1.0f / 7.0f);
        const float* rp = ref_polys + (size_t)bq * 8;
        float px = ((rp[0]*lam + rp[1])*lam + rp[2])*lam + rp[3];
        float py = ((rp[4]*lam + rp[5])*lam + rp[6])*lam + rp[7];
        float sx = 2.0f*(px - 0.5f), sy = 2.0f*(py - 0.5f);
        s_spt[tid*2 + 0] = sx;
        s_spt[tid*2 + 1] = sy;

        const int lvl = ref_levels[bq];
        const int H = c_lvl_h[lvl], W = H;
        const int base = b * NPIX_ + c_lvl_st[lvl];
        float gx = (sx + 1.0f) * 0.5f * (float)W - 0.5f;
        float gy = (sy + 1.0f) * 0.5f * (float)H - 0.5f;
        float x0 = floorf(gx), y0 = floorf(gy);
        float wx1 = gx - x0, wx0 = 1.0f - wx1;
        float wy1 = gy - y0, wy0 = 1.0f - wy1;
        #pragma unroll
        for (int k = 0; k < 4; k++) {
            float xf = (k & 1) ? (x0 + 1.0f) : x0;
            float yf = (k & 2) ? (y0 + 1.0f) : y0;
            float wx = (k & 1) ? wx1 : wx0;
            float wy = (k & 2) ? wy1 : wy0;
            bool valid = (xf >= 0.0f) && (xf <= (float)(W-1)) &&
                         (yf >= 0.0f) && (yf <= (float)(H-1));
            int xc = (int)fminf(fmaxf(xf, 0.0f), (float)(W-1));
            int yc = (int)fminf(fmaxf(yf, 0.0f), (float)(H-1));
            s_idx[tid*4 + k] = (base + yc * W + xc) * C_;
            s_w[tid*4 + k]   = valid ? (wy * wx) : 0.0f;
        }
    }
    b1s[tid]       = __ldg(b1 + tid);
    b1s[tid + 128] = __ldg(b1 + tid + 128);
    w2s[tid]       = __ldg((const float4*)W2 + tid);
    w2s[tid + 128] = __ldg((const float4*)W2 + tid + 128);
    __syncthreads();

    // ---- stage 2: gather -> A fp16 tile, XOR-swizzled rows of 512B ----
    // 64 threads per row-half; each thread owns a channel quad (LDG.128).
    {
        const int p4   = tid & 63;      // channel quad 0..63
        const int half = tid >> 6;      // rows [half*16, +16)
        #pragma unroll 4
        for (int r = 0; r < 16; r++) {
            const int m = half * 16 + r;
            int4   id = *(const int4*  )(s_idx + m * 4);
            float4 w  = *(const float4*)(s_w   + m * 4);
            float4 v0 = __ldg((const float4*)(memory + id.x) + p4);
            float4 v1 = __ldg((const float4*)(memory + id.y) + p4);
            float4 v2 = __ldg((const float4*)(memory + id.z) + p4);
            float4 v3 = __ldg((const float4*)(memory + id.w) + p4);
            float e0 = w.x*v0.x; e0 = fmaf(w.y, v1.x, e0);
            e0 = fmaf(w.z, v2.x, e0); e0 = fmaf(w.w, v3.x, e0);
            float e1 = w.x*v0.y; e1 = fmaf(w.y, v1.y, e1);
            e1 = fmaf(w.z, v2.y, e1); e1 = fmaf(w.w, v3.y, e1);
            float e2 = w.x*v0.z; e2 = fmaf(w.y, v1.z, e2);
            e2 = fmaf(w.z, v2.z, e2); e2 = fmaf(w.w, v3.z, e2);
            float e3 = w.x*v0.w; e3 = fmaf(w.y, v1.w, e3);
            e3 = fmaf(w.z, v2.w, e3); e3 = fmaf(w.w, v3.w, e3);

            uint2 h4;
            asm("cvt.rn.f16x2.f32 %0, %1, %2;" : "=r"(h4.x) : "f"(e1), "f"(e0));
            asm("cvt.rn.f16x2.f32 %0, %1, %2;" : "=r"(h4.y) : "f"(e3), "f"(e2));

            uint32_t byte = (uint32_t)m * 512u + (uint32_t)p4 * 8u;
            byte ^= (uint32_t)(m & 7) << 4;
            *(uint2*)(smem + SM_A + byte) = h4;
        }
    }
    __syncthreads();

    // ---- stage 3: fp16 HMMA GEMM1 (fp32 acc) + fused GEMM2 projection ----
    // warp wid: cols [wid*64, +64) in two 32-col chunks; bfr cached across mt
    // (B read once per warp), acc[2][4][4] live in the K loop.
    #pragma unroll
    for (int nc = 0; nc < 2; nc++) {
        const int nb = wid * 64 + nc * 32;
        float acc[2][4][4];
        #pragma unroll
        for (int mt = 0; mt < 2; mt++)
            #pragma unroll
            for (int nt = 0; nt < 4; nt++)
                #pragma unroll
                for (int d = 0; d < 4; d++) acc[mt][nt][d] = 0.0f;

        #pragma unroll 2
        for (int kk = 0; kk < 16; kk++) {
            uint2 bfr[4];
            #pragma unroll
            for (int nt = 0; nt < 4; nt++) {
                const int nn = (nb >> 3) + nt;
                bfr[nt] = __ldg(&g_w1b[(kk * 32 + nn) * 32 + lane]);
            }
            #pragma unroll
            for (int mt = 0; mt < 2; mt++) {
                const int jm = lane >> 3;
                const int mrow = mt * 16 + (lane & 7) + (jm & 1) * 8;
                const int kcol = kk * 16 + (jm >> 1) * 8;
                uint32_t byte = (uint32_t)mrow * 512u + (uint32_t)kcol * 2u;
                byte ^= (uint32_t)(mrow & 7) << 4;
                uint32_t af[4];
                ldmatrix_x4(af[0], af[1], af[2], af[3], sb + SM_A + byte);
                #pragma unroll
                for (int nt = 0; nt < 4; nt++)
                    mma_f16(acc[mt][nt], af, bfr[nt].x, bfr[nt].y);
            }
        }

        // chunk epilogue: tanh(d + b1) projected through W2
        #pragma unroll
        for (int mt = 0; mt < 2; mt++) {
            float p[2][4];
            #pragma unroll
            for (int rh = 0; rh < 2; rh++)
                #pragma unroll
                for (int j = 0; j < 4; j++) p[rh][j] = 0.0f;

            #pragma unroll
            for (int nt = 0; nt < 4; nt++)
                #pragma unroll
                for (int d = 0; d < 4; d++) {
                    const int col = nb + nt * 8 + (lane & 3) * 2 + (d & 1);
                    float h = fast_tanh(acc[mt][nt][d] + b1s[col]);
                    float4 w2 = w2s[col];
                    const int rh = d >> 1;
                    p[rh][0] = fmaf(h, w2.x, p[rh][0]);
                    p[rh][1] = fmaf(h, w2.y, p[rh][1]);
                    p[rh][2] = fmaf(h, w2.z, p[rh][2]);
                    p[rh][3] = fmaf(h, w2.w, p[rh][3]);
                }

            // reduce across the 4 lanes sharing a row (lane^1, lane^2)
            #pragma unroll
            for (int m = 1; m <= 2; m <<= 1)
                #pragma unroll
                for (int rh = 0; rh < 2; rh++)
                    #pragma unroll
                    for (int j = 0; j < 4; j++)
                        p[rh][j] += __shfl_xor_sync(0xffffffffu, p[rh][j], m);

            if ((lane & 3) == 0) {
                #pragma unroll
                for (int rh = 0; rh < 2; rh++) {
                    const int row = mt * 16 + (lane >> 2) + 8 * rh;
                    float4 v = make_float4(p[rh][0], p[rh][1], p[rh][2], p[rh][3]);
                    if (nc == 0) {
                        s_part[wid * 32 + row] = v;
                    } else {
                        float4 o = s_part[wid * 32 + row];
                        o.x += v.x; o.y += v.y; o.z += v.z; o.w += v.w;
                        s_part[wid * 32 + row] = o;
                    }
                }
            }
        }
    }
    __syncthreads();

    // ---- stage 4: final combine + output (threads 0..31, one M-row each) ----
    if (tid < ROWS) {
        float4 a0 = s_part[0 * 32 + tid];
        float4 a1 = s_part[1 * 32 + tid];
        float4 a2 = s_part[2 * 32 + tid];
        float4 a3 = s_part[3 * 32 + tid];
        float v0 = a0.x + a1.x + a2.x + a3.x;
        float v1 = a0.y + a1.y + a2.y + a3.y;
        float v2 = a0.z + a1.z + a2.z + a3.z;
        float v3 = a0.w + a1.w + a2.w + a3.w;
        const int qi = tid >> 3, s = tid & 7;
        const float sx = s_spt[tid*2 + 0], sy = s_spt[tid*2 + 1];
        float4 bb = __ldg((const float4*)b2);
        float4 o;
        o.x = SSCALE * fast_tanh(v0 + bb.x) + sx;
        o.y = SSCALE * fast_tanh(v1 + bb.y) + sy;
        o.z = SSCALE * fast_tanh(v2 + bb.z) + sx;
        o.w = SSCALE * fast_tanh(v3 + bb.w) + sy;
        *(float4*)(out + (size_t)(bq0 + qi) * 32 + s * 4) = o;
    }
}

extern "C" void kernel_launch(void* const* d_in, const int* in_sizes, int n_in,
                              void* d_out, int out_size)
{
    const float* ref_polys  = (const float*)d_in[0];
    const int*   ref_levels = (const int*  )d_in[1];
    const float* memory     = (const float*)d_in[2];
    const float* W1         = (const float*)d_in[3];
    const float* b1         = (const float*)d_in[4];
    const float* W2         = (const float*)d_in[5];
    const float* b2         = (const float*)d_in[6];
    float* out = (float*)d_out;

    prep_w1<<<64, 256>>>(W1);   // 16384 threads = one per g_w1b entry
    decoder_kernel<<<(B_ * Q_) / QPB, 128, SM_TOTAL>>>(
        ref_polys, ref_levels, memory, b1, W2, b2, out);
}